// round 13
// baseline (speedup 1.0000x reference)
#include <cuda_runtime.h>
#include <math.h>

// ChamferReward — R12: j-quartered tasks to fix wave quantization.
// Model (fits issue/fma/L1 of R8-R11): FFMA2 has 3 even + 3 odd distinct source
// regs -> RF-bank rt=3; compute floor ~174us; remaining gap is the 2-wave
// quantization of 1024 unit tasks over 592 CTA slots. Fix: 4096 CTAs, each
// (slice, direction, j-quarter): 128 jp staged (7KB smem), same bit-identical
// inner loop. Each quarter emits (bestd, xd) per item; merge kernel picks the
// first strict-min quarter (ascending q = ascending j => exact jnp.argmin
// first-occurrence semantics) and reduces.

#define N_PART  1024
#define NJ_Q    256             // j per quarter
#define NJP_Q   128             // jp per quarter
#define THREADS 128
#define ITEMS   8
#define CJP     8               // jp per chunk (16 j)
#define NCHUNK_Q (NJP_Q / CJP)  // 16
#define NQ      4
#define NBVP    1024            // (bv, pass) pairs
#define NCTA_PASS (NBVP * NQ)   // 4096

typedef unsigned long long ull;

__device__ float2 g_rec[(size_t)NBVP * N_PART * NQ];  // (bestd, xd) — 32MB scratch
__device__ float  g_partials[NBVP];
__device__ unsigned int g_arrived = 0;

#define FMA2(d, a, b, c) \
    asm("fma.rn.f32x2 %0, %1, %2, %3;" : "=l"(d) : "l"(a), "l"(b), "l"(c))

__device__ __forceinline__ ull pack_dup(float x) {
    ull r;
    unsigned xi = __float_as_uint(x);
    asm("mov.b64 %0, {%1, %1};" : "=l"(r) : "r"(xi));
    return r;
}

__device__ __forceinline__ void unpack2(ull v, float& lo, float& hi) {
    unsigned a, b;
    asm("mov.b64 {%0, %1}, %2;" : "=r"(a), "=r"(b) : "l"(v));
    lo = __uint_as_float(a);
    hi = __uint_as_float(b);
}

__global__ void __launch_bounds__(THREADS, 4)
chamfer_pass_kernel(const float* __restrict__ achieved,
                    const float* __restrict__ desired,
                    const float* __restrict__ norm_mean,
                    const float* __restrict__ norm_std)
{
    __shared__ ulonglong2 sb01[NJP_Q];   // 2KB: {b0 pair, b1 pair}
    __shared__ ulonglong2 sb23[NJP_Q];   // 2KB: {b2 pair, b3 pair}
    __shared__ ull        sbb[NJP_Q];    // 1KB: |b|^2 pair
    __shared__ float2     sxy[NJ_Q];     // 2KB

    const int q    = blockIdx.x & 3;     // j-quarter
    const int bvp  = blockIdx.x >> 2;    // (bv, pass)
    const int pass = bvp & 1;
    const int bv   = bvp >> 1;

    const float* ownp;
    const float* strp;
    if (pass == 0) { ownp = desired;  strp = achieved; }
    else           { ownp = achieved; strp = desired;  }
    const size_t base = (size_t)bv * (size_t)N_PART * 10;
    ownp += base;
    strp += base + (size_t)q * NJ_Q * 10;

    const float m0 = __ldg(norm_mean + 0), m1 = __ldg(norm_mean + 1);
    const float m5 = __ldg(norm_mean + 5), m6 = __ldg(norm_mean + 6);
    const float m7 = __ldg(norm_mean + 7), m8 = __ldg(norm_mean + 8);
    const float s0 = __ldg(norm_std  + 0), s1 = __ldg(norm_std  + 1);
    const float s5 = __ldg(norm_std  + 5), s6 = __ldg(norm_std  + 6);
    const float s7 = __ldg(norm_std  + 7), s8 = __ldg(norm_std  + 8);

    const int tid = threadIdx.x;

    // ---- Stage this quarter's streamed rows (normalize, precompute |b|^2) ----
    {
        float* f01 = (float*)sb01;   // per jp: [b0_lo, b0_hi, b1_lo, b1_hi]
        float* f23 = (float*)sb23;   // per jp: [b2_lo, b2_hi, b3_lo, b3_hi]
        float* fbb = (float*)sbb;    // contiguous over local j
        for (int jl = tid; jl < NJ_Q; jl += THREADS) {
            const float2* r2 = (const float2*)(strp + (size_t)jl * 10);
            const float2 q0 = r2[0];   // r0, r1
            const float2 q1 = r2[2];   // r4, r5
            const float2 q2 = r2[3];   // r6, r7
            const float2 q3 = r2[4];   // r8, r9
            float x0 = fmaf(q0.x, s0, m0);
            float x1 = fmaf(q0.y, s1, m1);
            float v0 = fmaf(q1.y, s5, m5);
            float v1 = fmaf(q2.x, s6, m6);
            float v2 = fmaf(q2.y, s7, m7);
            float v3 = fmaf(q3.x, s8, m8);
            const int jp = jl >> 1, h = jl & 1;
            f01[jp * 4 + h]     = v0;
            f01[jp * 4 + 2 + h] = v1;
            f23[jp * 4 + h]     = v2;
            f23[jp * 4 + 2 + h] = v3;
            fbb[jl] = v0 * v0 + v1 * v1 + v2 * v2 + v3 * v3;
            sxy[jl] = make_float2(x0, x1);
        }
    }

    // ---- Owned items: a' = -2a, duplicated into both packed halves ----
    ull a0d[ITEMS], a1d[ITEMS], a2d[ITEMS], a3d[ITEMS];
#pragma unroll
    for (int k = 0; k < ITEMS; k++) {
        const int i = tid + k * THREADS;
        const float2* r2 = (const float2*)(ownp + (size_t)i * 10);
        const float2 q1 = r2[2];
        const float2 q2 = r2[3];
        const float2 q3 = r2[4];
        float a0 = fmaf(q1.y, s5, m5);
        float a1 = fmaf(q2.x, s6, m6);
        float a2 = fmaf(q2.y, s7, m7);
        float a3 = fmaf(q3.x, s8, m8);
        a0d[k] = pack_dup(-2.0f * a0);
        a1d[k] = pack_dup(-2.0f * a1);
        a2d[k] = pack_dup(-2.0f * a2);
        a3d[k] = pack_dup(-2.0f * a3);
    }

    __syncthreads();

    // ---- Main loop: 16 chunks x 8 jp, single-chain chunk minima ----
    float bestd[ITEMS];
    unsigned bcp = 0;               // 8 x 4-bit packed chunk ids (ch < 16)
#pragma unroll
    for (int k = 0; k < ITEMS; k++) bestd[k] = 3.4e38f;

    for (int ch = 0; ch < NCHUNK_Q; ch++) {
        float cm[ITEMS];
#pragma unroll
        for (int k = 0; k < ITEMS; k++) cm[k] = 3.4e38f;

#pragma unroll
        for (int u = 0; u < CJP; u++) {
            const int jp = ch * CJP + u;
            const ulonglong2 p01 = sb01[jp];
            const ulonglong2 p23 = sb23[jp];
            const ull        acc = sbb[jp];
#pragma unroll
            for (int k = 0; k < ITEMS; k++) {
                ull t;
                FMA2(t, a0d[k], p01.x, acc);
                FMA2(t, a1d[k], p01.y, t);
                FMA2(t, a2d[k], p23.x, t);
                FMA2(t, a3d[k], p23.y, t);
                float lo, hi;
                unpack2(t, lo, hi);                  // register-naming only
                cm[k] = fminf(cm[k], fminf(lo, hi)); // inner fmin not loop-carried
            }
        }
#pragma unroll
        for (int k = 0; k < ITEMS; k++) {
            if (cm[k] < bestd[k]) {                  // strict <: first chunk wins
                bestd[k] = cm[k];
                bcp = (bcp & ~(15u << (k * 4))) | ((unsigned)ch << (k * 4));
            }
        }
    }

    // ---- Tail: rescan winner chunk (bit-identical), emit (bestd, xd) ----
#pragma unroll
    for (int k = 0; k < ITEMS; k++) {
        const int i = tid + k * THREADS;
        const float2* r2 = (const float2*)(ownp + (size_t)i * 10);
        const float2 q0 = r2[0];
        const float2 q1 = r2[2];
        const float2 q2 = r2[3];
        const float2 q3 = r2[4];
        const float ox = fmaf(q0.x, s0, m0);
        const float oy = fmaf(q0.y, s1, m1);
        const float a0 = fmaf(q1.y, s5, m5);
        const float a1 = fmaf(q2.x, s6, m6);
        const float a2 = fmaf(q2.y, s7, m7);
        const float a3 = fmaf(q3.x, s8, m8);
        const float aa = a0 * a0 + a1 * a1 + a2 * a2 + a3 * a3;

        const float bd = bestd[k];
        const int jp0 = (int)((bcp >> (k * 4)) & 15u) * CJP;
        int jbest = jp0 * 2;
        bool found = false;
        for (int u = 0; u < CJP; u++) {
            const int jp = jp0 + u;
            const ulonglong2 p01 = sb01[jp];
            const ulonglong2 p23 = sb23[jp];
            const ull        acc = sbb[jp];
            ull t;
            FMA2(t, a0d[k], p01.x, acc);
            FMA2(t, a1d[k], p01.y, t);
            FMA2(t, a2d[k], p23.x, t);
            FMA2(t, a3d[k], p23.y, t);
            float lo, hi;
            unpack2(t, lo, hi);
            if (!found && lo == bd) { jbest = jp * 2;     found = true; }
            if (!found && hi == bd) { jbest = jp * 2 + 1; found = true; }
        }

        const float2 p = sxy[jbest];
        const float dx = ox - p.x;
        const float dy = oy - p.y;
        float xd = sqrtf(dx * dx + dy * dy);
        const float min_d = aa + bd;        // quarter-min squared latent dist;
        if (min_d > 6.0f) xd = 1.0f;        // winner quarter's bd == global min
        g_rec[((size_t)bvp * N_PART + (size_t)i) * NQ + q] = make_float2(bd, xd);
    }
}

__global__ void __launch_bounds__(256)
chamfer_merge_kernel(float* __restrict__ out)
{
    __shared__ float warp_sums[8];
    __shared__ unsigned int s_rank;

    const int bvp = blockIdx.x;
    const int tid = threadIdx.x;

    // Thread handles 4 consecutive items -> 16 contiguous float2 (128B).
    const float2* basep = g_rec + (size_t)bvp * N_PART * NQ + (size_t)tid * 4 * NQ;
    float sum = 0.0f;
#pragma unroll
    for (int i = 0; i < 4; i++) {
        float2 r = basep[i * NQ];
        float bd = r.x, xd = r.y;
#pragma unroll
        for (int qq = 1; qq < NQ; qq++) {
            float2 s = basep[i * NQ + qq];
            if (s.x < bd) { bd = s.x; xd = s.y; }   // strict <: first quarter wins
        }
        sum += xd;
    }

#pragma unroll
    for (int off = 16; off > 0; off >>= 1)
        sum += __shfl_down_sync(0xffffffffu, sum, off);
    if ((tid & 31) == 0) warp_sums[tid >> 5] = sum;
    __syncthreads();
    if (tid == 0) {
        float s = 0.0f;
#pragma unroll
        for (int w = 0; w < 8; w++) s += warp_sums[w];
        g_partials[bvp] = s;
        __threadfence();
        s_rank = atomicAdd(&g_arrived, 1u);   // last block finalizes
    }
    __syncthreads();

    if (s_rank == NBVP - 1) {
        __threadfence();                     // acquire partials
        if (tid < 128) {
            float s = 0.0f;
#pragma unroll
            for (int t = 0; t < 8; t++) s += g_partials[tid * 8 + t];
            out[tid] = -s * (1.0f / (1024.0f * 8.0f));
        }
        __syncthreads();
        if (tid == 0) g_arrived = 0;         // reset for next graph replay
    }
}

extern "C" void kernel_launch(void* const* d_in, const int* in_sizes, int n_in,
                              void* d_out, int out_size)
{
    const float* achieved  = (const float*)d_in[0];
    const float* desired   = (const float*)d_in[1];
    const float* norm_mean = (const float*)d_in[2];
    const float* norm_std  = (const float*)d_in[3];
    float* out = (float*)d_out;

    chamfer_pass_kernel<<<NCTA_PASS, THREADS>>>(achieved, desired, norm_mean, norm_std);
    chamfer_merge_kernel<<<NBVP, 256>>>(out);
}

// round 14
// speedup vs baseline: 1.4432x; 1.4432x over previous
#include <cuda_runtime.h>
#include <math.h>

// ChamferReward — R13: owned-item task split for wave utilization.
// R11 runs within ~10% of its FFMA2 RF-bank floor (rt~3); remaining slack is
// 1024 tasks over 592 slots = 86.5% utilization. Split each task's OWNED side
// in half (j-axis split failed in R12: it multiplies owned-side overhead):
// 2048 tasks x (512 items, full 1024 j), THREADS=64, ITEMS=8 -> identical
// 32-FFMA2-per-3-LDS inner loop; smem 28.7KB -> 7 CTAs/SM -> 1036 slots ->
// 98.8% utilization. Values bit-identical to R11; partials regrouped 16/batch.

#define N_PART  1024
#define NJP     512
#define THREADS 64
#define ITEMS   8
#define CJP     8               // jp per chunk (16 j)
#define NCHUNK  (NJP / CJP)     // 64
#define NCTA    2048

typedef unsigned long long ull;

__device__ float g_partials[NCTA];
__device__ unsigned int g_arrived = 0;

#define FMA2(d, a, b, c) \
    asm("fma.rn.f32x2 %0, %1, %2, %3;" : "=l"(d) : "l"(a), "l"(b), "l"(c))

__device__ __forceinline__ ull pack_dup(float x) {
    ull r;
    unsigned xi = __float_as_uint(x);
    asm("mov.b64 %0, {%1, %1};" : "=l"(r) : "r"(xi));
    return r;
}

__device__ __forceinline__ void unpack2(ull v, float& lo, float& hi) {
    unsigned a, b;
    asm("mov.b64 {%0, %1}, %2;" : "=r"(a), "=r"(b) : "l"(v));
    lo = __uint_as_float(a);
    hi = __uint_as_float(b);
}

__global__ void __launch_bounds__(THREADS, 7)
chamfer_pass_kernel(const float* __restrict__ achieved,
                    const float* __restrict__ desired,
                    const float* __restrict__ norm_mean,
                    const float* __restrict__ norm_std,
                    float* __restrict__ out)
{
    __shared__ ulonglong2 sb01[NJP];   // 8KB: {b0 pair, b1 pair}
    __shared__ ulonglong2 sb23[NJP];   // 8KB: {b2 pair, b3 pair}
    __shared__ ull        sbb[NJP];    // 4KB: |b|^2 pair
    __shared__ float2     sxy[N_PART]; // 8KB
    __shared__ float      warp_sums[THREADS / 32];
    __shared__ unsigned int s_rank;

    const int c    = blockIdx.x;
    const int half = c & 1;            // owned-item half
    const int bvp  = c >> 1;
    const int pass = bvp & 1;
    const int bv   = bvp >> 1;

    const float* ownp;
    const float* strp;
    if (pass == 0) { ownp = desired;  strp = achieved; }
    else           { ownp = achieved; strp = desired;  }
    const size_t base = (size_t)bv * (size_t)N_PART * 10;
    ownp += base + (size_t)half * 512 * 10;
    strp += base;

    const float m0 = __ldg(norm_mean + 0), m1 = __ldg(norm_mean + 1);
    const float m5 = __ldg(norm_mean + 5), m6 = __ldg(norm_mean + 6);
    const float m7 = __ldg(norm_mean + 7), m8 = __ldg(norm_mean + 8);
    const float s0 = __ldg(norm_std  + 0), s1 = __ldg(norm_std  + 1);
    const float s5 = __ldg(norm_std  + 5), s6 = __ldg(norm_std  + 6);
    const float s7 = __ldg(norm_std  + 7), s8 = __ldg(norm_std  + 8);

    const int tid = threadIdx.x;

    // ---- Stage full streamed side (normalize, precompute |b|^2) ----
    {
        float* f01 = (float*)sb01;   // per jp: [b0_lo, b0_hi, b1_lo, b1_hi]
        float* f23 = (float*)sb23;   // per jp: [b2_lo, b2_hi, b3_lo, b3_hi]
        float* fbb = (float*)sbb;    // contiguous over j
        for (int i = tid; i < N_PART; i += THREADS) {
            const float2* r2 = (const float2*)(strp + (size_t)i * 10);
            const float2 q0 = r2[0];   // r0, r1
            const float2 q1 = r2[2];   // r4, r5
            const float2 q2 = r2[3];   // r6, r7
            const float2 q3 = r2[4];   // r8, r9
            float x0 = fmaf(q0.x, s0, m0);
            float x1 = fmaf(q0.y, s1, m1);
            float v0 = fmaf(q1.y, s5, m5);
            float v1 = fmaf(q2.x, s6, m6);
            float v2 = fmaf(q2.y, s7, m7);
            float v3 = fmaf(q3.x, s8, m8);
            const int jp = i >> 1, h = i & 1;
            f01[jp * 4 + h]     = v0;
            f01[jp * 4 + 2 + h] = v1;
            f23[jp * 4 + h]     = v2;
            f23[jp * 4 + 2 + h] = v3;
            fbb[i] = v0 * v0 + v1 * v1 + v2 * v2 + v3 * v3;
            sxy[i] = make_float2(x0, x1);
        }
    }

    // ---- Owned items (this CTA's 512-item half): a' = -2a, dup packed ----
    ull a0d[ITEMS], a1d[ITEMS], a2d[ITEMS], a3d[ITEMS];
#pragma unroll
    for (int k = 0; k < ITEMS; k++) {
        const int i = tid + k * THREADS;
        const float2* r2 = (const float2*)(ownp + (size_t)i * 10);
        const float2 q1 = r2[2];
        const float2 q2 = r2[3];
        const float2 q3 = r2[4];
        float a0 = fmaf(q1.y, s5, m5);
        float a1 = fmaf(q2.x, s6, m6);
        float a2 = fmaf(q2.y, s7, m7);
        float a3 = fmaf(q3.x, s8, m8);
        a0d[k] = pack_dup(-2.0f * a0);
        a1d[k] = pack_dup(-2.0f * a1);
        a2d[k] = pack_dup(-2.0f * a2);
        a3d[k] = pack_dup(-2.0f * a3);
    }

    __syncthreads();

    // ---- Main loop: single-chain value-only chunk minima ----
    float bestd[ITEMS];
    ull bcp = 0;                    // 8 x 6-bit packed chunk ids
#pragma unroll
    for (int k = 0; k < ITEMS; k++) bestd[k] = 3.4e38f;

    for (int ch = 0; ch < NCHUNK; ch++) {
        float cm[ITEMS];
#pragma unroll
        for (int k = 0; k < ITEMS; k++) cm[k] = 3.4e38f;

#pragma unroll
        for (int u = 0; u < CJP; u++) {
            const int jp = ch * CJP + u;
            const ulonglong2 p01 = sb01[jp];
            const ulonglong2 p23 = sb23[jp];
            const ull        acc = sbb[jp];
#pragma unroll
            for (int k = 0; k < ITEMS; k++) {
                ull t;
                FMA2(t, a0d[k], p01.x, acc);
                FMA2(t, a1d[k], p01.y, t);
                FMA2(t, a2d[k], p23.x, t);
                FMA2(t, a3d[k], p23.y, t);
                float lo, hi;
                unpack2(t, lo, hi);                  // register-naming only
                cm[k] = fminf(cm[k], fminf(lo, hi)); // inner fmin not loop-carried
            }
        }
#pragma unroll
        for (int k = 0; k < ITEMS; k++) {
            if (cm[k] < bestd[k]) {                  // strict <: first chunk wins
                bestd[k] = cm[k];
                bcp = (bcp & ~(63ull << (k * 6))) | ((ull)(unsigned)ch << (k * 6));
            }
        }
    }

    // ---- Tail: recompute own xy/|a|^2 (bit-identical), rescan, sum ----
    float partial = 0.0f;
#pragma unroll
    for (int k = 0; k < ITEMS; k++) {
        const int i = tid + k * THREADS;
        const float2* r2 = (const float2*)(ownp + (size_t)i * 10);
        const float2 q0 = r2[0];
        const float2 q1 = r2[2];
        const float2 q2 = r2[3];
        const float2 q3 = r2[4];
        const float ox = fmaf(q0.x, s0, m0);
        const float oy = fmaf(q0.y, s1, m1);
        const float a0 = fmaf(q1.y, s5, m5);
        const float a1 = fmaf(q2.x, s6, m6);
        const float a2 = fmaf(q2.y, s7, m7);
        const float a3 = fmaf(q3.x, s8, m8);
        const float aa = a0 * a0 + a1 * a1 + a2 * a2 + a3 * a3;

        const float bd = bestd[k];
        const int jp0 = (int)((bcp >> (k * 6)) & 63ull) * CJP;
        int jbest = jp0 * 2;
        bool found = false;
        for (int u = 0; u < CJP; u++) {
            const int jp = jp0 + u;
            const ulonglong2 p01 = sb01[jp];
            const ulonglong2 p23 = sb23[jp];
            const ull        acc = sbb[jp];
            ull t;
            FMA2(t, a0d[k], p01.x, acc);
            FMA2(t, a1d[k], p01.y, t);
            FMA2(t, a2d[k], p23.x, t);
            FMA2(t, a3d[k], p23.y, t);
            float lo, hi;
            unpack2(t, lo, hi);
            if (!found && lo == bd) { jbest = jp * 2;     found = true; }
            if (!found && hi == bd) { jbest = jp * 2 + 1; found = true; }
        }

        const float2 p = sxy[jbest];
        const float dx = ox - p.x;
        const float dy = oy - p.y;
        float xd = sqrtf(dx * dx + dy * dy);
        const float min_d = aa + bd;        // true squared latent distance
        if (min_d > 6.0f) xd = 1.0f;        // LATENT_DIST_THRESHOLD
        partial += xd;
    }

    // ---- Block reduce (deterministic) ----
#pragma unroll
    for (int off = 16; off > 0; off >>= 1)
        partial += __shfl_down_sync(0xffffffffu, partial, off);
    if ((tid & 31) == 0) warp_sums[tid >> 5] = partial;
    __syncthreads();
    if (tid == 0) {
        float s = 0.0f;
#pragma unroll
        for (int w = 0; w < THREADS / 32; w++) s += warp_sums[w];
        g_partials[c] = s;
        __threadfence();
        s_rank = atomicAdd(&g_arrived, 1u);   // last CTA reduces
    }
    __syncthreads();

    if (s_rank == NCTA - 1) {
        __threadfence();                    // acquire partials
        // 64 threads: each reduces 2 batch elements (16 partials each).
#pragma unroll
        for (int r = 0; r < 2; r++) {
            const int b = tid * 2 + r;
            float s = 0.0f;
#pragma unroll
            for (int t = 0; t < 16; t++) s += g_partials[b * 16 + t];
            out[b] = -s * (1.0f / (1024.0f * 8.0f));
        }
        __syncthreads();
        if (tid == 0) g_arrived = 0;        // reset for next graph replay
    }
}

extern "C" void kernel_launch(void* const* d_in, const int* in_sizes, int n_in,
                              void* d_out, int out_size)
{
    const float* achieved  = (const float*)d_in[0];
    const float* desired   = (const float*)d_in[1];
    const float* norm_mean = (const float*)d_in[2];
    const float* norm_std  = (const float*)d_in[3];
    float* out = (float*)d_out;

    chamfer_pass_kernel<<<NCTA, THREADS>>>(achieved, desired, norm_mean, norm_std, out);
}